// round 6
// baseline (speedup 1.0000x reference)
#include <cuda_runtime.h>
#include <cuda_bf16.h>
#include <math.h>
#include <stdint.h>

#define NMAX      500000
#define DIM       128
#define SNEG      256
#define BSTRIDE   136          // byte stride of int8 B rows in smem (conflict-free)
#define MTILE     256          // rows per block
#define INV_T     10.0f
#define LOG_S     5.545177444479562f   // log(256)
#define MAXBLOCKS 4096

// Scratch: int8 quantized embeddings (64MB) + per-row dequant scale (2MB).
// cos(a,b) = dot_int8(a,b) * sc[a] * sc[b]
__device__ int8_t g_Qi[(size_t)NMAX * DIM];
__device__ float  g_sc[NMAX];
__device__ float  g_partial[MAXBLOCKS];
__device__ int    g_idx_is64;

// ---------------------------------------------------------------------------
// Kernel 0: detect index dtype (int32 vs int64) from first 1KB of negatives.
// ---------------------------------------------------------------------------
__global__ void detect_idx_kernel(const void* __restrict__ neg, int n) {
    const long long* p = (const long long*)neg;
    long long v = p[threadIdx.x];              // 128 threads -> 1KB
    int ok = (v >= 0 && v < (long long)n);
    int all = __syncthreads_and(ok);
    if (threadIdx.x == 0) g_idx_is64 = all;
}

__device__ __forceinline__ long long load_index(const void* p, long long i, int is64) {
    return is64 ? ((const long long*)p)[i] : (long long)((const int*)p)[i];
}

// ---------------------------------------------------------------------------
// Kernel 1: normalize + int8 quantize. One warp per row.
//   q_i = rint(127 * x_i / max|x|)   (normalization cancels in the ratio)
//   sc  = (max|x| * inv_norm) / 127  so that dot*sc_a*sc_b = cosine
// ---------------------------------------------------------------------------
__global__ void quantize_kernel(const float* __restrict__ E, int n) {
    int row  = (int)((blockIdx.x * (long long)blockDim.x + threadIdx.x) >> 5);
    int lane = threadIdx.x & 31;
    if (row >= n) return;
    float4 v = reinterpret_cast<const float4*>(E + (size_t)row * DIM)[lane];
    float ss = v.x * v.x + v.y * v.y + v.z * v.z + v.w * v.w;
    float ma = fmaxf(fmaxf(fabsf(v.x), fabsf(v.y)), fmaxf(fabsf(v.z), fabsf(v.w)));
#pragma unroll
    for (int o = 16; o > 0; o >>= 1) {
        ss += __shfl_xor_sync(0xffffffffu, ss, o);
        ma  = fmaxf(ma, __shfl_xor_sync(0xffffffffu, ma, o));
    }
    float inv = 1.0f / fmaxf(sqrtf(ss), 1e-12f);
    float qs  = 127.0f / fmaxf(ma, 1e-20f);
    int q0 = __float2int_rn(v.x * qs);
    int q1 = __float2int_rn(v.y * qs);
    int q2 = __float2int_rn(v.z * qs);
    int q3 = __float2int_rn(v.w * qs);
    unsigned packed = (unsigned)(q0 & 0xFF) | ((unsigned)(q1 & 0xFF) << 8)
                    | ((unsigned)(q2 & 0xFF) << 16) | ((unsigned)(q3 & 0xFF) << 24);
    reinterpret_cast<unsigned*>(g_Qi + (size_t)row * DIM)[lane] = packed;
    if (lane == 0) g_sc[row] = ma * inv * (1.0f / 127.0f);
}

// ---------------------------------------------------------------------------
// Kernel 2: per 256-row tile — int8 IMMA GEMM vs 256 negatives + positives via
// dp4a + fused logsumexp (|logit|<=10, no max needed). Warp = 32 rows.
// ---------------------------------------------------------------------------
__global__ __launch_bounds__(256, 2) void main_kernel(
    const void* __restrict__ pos_idx,
    const void* __restrict__ neg_idx,
    int n)
{
    __shared__ int8_t sB[SNEG * BSTRIDE];     // 34816 B
    __shared__ float  sSc[SNEG];              // negative dequant scales
    __shared__ float  sScRow[MTILE];          // row scales * INV_T
    __shared__ float  sPos[MTILE];
    __shared__ float  sRed[8];

    const int tid  = threadIdx.x;
    const int lane = tid & 31;
    const int warp = tid >> 5;
    const long long tile0 = (long long)blockIdx.x * MTILE;
    const int is64 = g_idx_is64;

    // ---- stage 256 negatives (int8 rows, byte stride 136) + their scales ----
    {
        long long vr = load_index(neg_idx, tid, is64);
        const uint2* src = reinterpret_cast<const uint2*>(g_Qi + (size_t)vr * DIM);
        char* dst = (char*)sB + tid * BSTRIDE;
#pragma unroll
        for (int j = 0; j < 16; j++)
            *reinterpret_cast<uint2*>(dst + j * 8) = src[j];
        sSc[tid] = g_sc[vr];
    }

    // ---- row scales + positive logits via dp4a (1 thread per row) ----------
    {
        long long row = tile0 + tid;
        float posl = 0.0f, srow = 0.0f;
        if (row < n) {
            srow = g_sc[row] * INV_T;
            long long p = load_index(pos_idx, row, is64);
            const uint2* qa = reinterpret_cast<const uint2*>(g_Qi + (size_t)row * DIM);
            const uint2* qb = reinterpret_cast<const uint2*>(g_Qi + (size_t)p * DIM);
            int dot = 0;
#pragma unroll
            for (int j = 0; j < 16; j++) {
                uint2 a = qa[j], b = qb[j];
                dot = __dp4a((int)a.x, (int)b.x, dot);
                dot = __dp4a((int)a.y, (int)b.y, dot);
            }
            posl = (float)dot * srow * g_sc[p];
        }
        sScRow[tid] = srow;
        sPos[tid]   = posl;
    }
    __syncthreads();

    // ---- GEMM: warp = 32 rows (2 x 16-row MMA tiles) x 256 negs -------------
    const int g  = lane >> 2;     // 0..7
    const int t4 = lane & 3;      // 0..3
    const int rbase = warp * 32;
    const long long rowG = tile0 + rbase + g;

    // per-row dequant scales (includes INV_T)
    float srw[2][2];
#pragma unroll
    for (int T = 0; T < 2; T++) {
        srw[T][0] = sScRow[rbase + g + 16 * T];
        srw[T][1] = sScRow[rbase + g + 16 * T + 8];
    }

    float rs[2][2] = {{0.f, 0.f}, {0.f, 0.f}};

#pragma unroll
    for (int c = 0; c < 4; c++) {
        int acc[2][8][4];
#pragma unroll
        for (int T = 0; T < 2; T++)
#pragma unroll
            for (int i = 0; i < 8; i++) {
                acc[T][i][0] = 0; acc[T][i][1] = 0;
                acc[T][i][2] = 0; acc[T][i][3] = 0;
            }

#pragma unroll
        for (int k0 = 0; k0 < 4; k0++) {
            const int kb = k0 * 32 + t4 * 4;
            unsigned afr[2][4];
#pragma unroll
            for (int T = 0; T < 2; T++) {
                long long r0 = rowG + 16 * T;
                long long r1 = r0 + 8;
                bool v0 = r0 < n, v1 = r1 < n;
                const char* p0 = (const char*)g_Qi + (size_t)r0 * DIM + kb;
                const char* p1 = (const char*)g_Qi + (size_t)r1 * DIM + kb;
                afr[T][0] = v0 ? *reinterpret_cast<const unsigned*>(p0) : 0u;
                afr[T][1] = v1 ? *reinterpret_cast<const unsigned*>(p1) : 0u;
                afr[T][2] = v0 ? *reinterpret_cast<const unsigned*>(p0 + 16) : 0u;
                afr[T][3] = v1 ? *reinterpret_cast<const unsigned*>(p1 + 16) : 0u;
            }
#pragma unroll
            for (int nt = 0; nt < 8; nt++) {
                const char* bp = (const char*)sB
                               + (c * 64 + nt * 8 + g) * BSTRIDE + kb;
                unsigned b0 = *reinterpret_cast<const unsigned*>(bp);
                unsigned b1 = *reinterpret_cast<const unsigned*>(bp + 16);
#pragma unroll
                for (int T = 0; T < 2; T++) {
                    asm volatile(
                        "mma.sync.aligned.m16n8k32.row.col.s32.s8.s8.s32 "
                        "{%0,%1,%2,%3}, {%4,%5,%6,%7}, {%8,%9}, {%0,%1,%2,%3};\n"
                        : "+r"(acc[T][nt][0]), "+r"(acc[T][nt][1]),
                          "+r"(acc[T][nt][2]), "+r"(acc[T][nt][3])
                        : "r"(afr[T][0]), "r"(afr[T][1]),
                          "r"(afr[T][2]), "r"(afr[T][3]),
                          "r"(b0), "r"(b1));
                }
            }
        }

        // ---- epilogue for this 64-neg chunk: dequant + exp-accumulate ----
#pragma unroll
        for (int nt = 0; nt < 8; nt++) {
            float2 sc2 = *reinterpret_cast<const float2*>(
                sSc + c * 64 + nt * 8 + t4 * 2);
#pragma unroll
            for (int T = 0; T < 2; T++) {
                rs[T][0] += __expf((float)acc[T][nt][0] * srw[T][0] * sc2.x)
                          + __expf((float)acc[T][nt][1] * srw[T][0] * sc2.y);
                rs[T][1] += __expf((float)acc[T][nt][2] * srw[T][1] * sc2.x)
                          + __expf((float)acc[T][nt][3] * srw[T][1] * sc2.y);
            }
        }
    }

    // reduce exp-sums across the 4 lanes of each row group
#pragma unroll
    for (int T = 0; T < 2; T++) {
        rs[T][0] += __shfl_xor_sync(0xffffffffu, rs[T][0], 1);
        rs[T][0] += __shfl_xor_sync(0xffffffffu, rs[T][0], 2);
        rs[T][1] += __shfl_xor_sync(0xffffffffu, rs[T][1], 1);
        rs[T][1] += __shfl_xor_sync(0xffffffffu, rs[T][1], 2);
    }

    float contrib = 0.0f;
    if (t4 == 0) {
#pragma unroll
        for (int T = 0; T < 2; T++) {
            long long r0 = rowG + 16 * T;
            if (r0 < n)
                contrib += sPos[rbase + g + 16 * T]     - (logf(rs[T][0]) - LOG_S);
            if (r0 + 8 < n)
                contrib += sPos[rbase + g + 16 * T + 8] - (logf(rs[T][1]) - LOG_S);
        }
    }
#pragma unroll
    for (int o = 16; o > 0; o >>= 1)
        contrib += __shfl_xor_sync(0xffffffffu, contrib, o);
    if (lane == 0) sRed[warp] = contrib;
    __syncthreads();
    if (tid == 0) {
        float s = 0.0f;
#pragma unroll
        for (int w = 0; w < 8; w++) s += sRed[w];
        g_partial[blockIdx.x] = s;
    }
}

// ---------------------------------------------------------------------------
// Kernel 3: deterministic final reduction, loss = -sum / N
// ---------------------------------------------------------------------------
__global__ void finalize_kernel(float* __restrict__ out, int n, int nblocks) {
    __shared__ float sh[256];
    float s = 0.0f;
    for (int i = threadIdx.x; i < nblocks; i += 256) s += g_partial[i];
    sh[threadIdx.x] = s;
    __syncthreads();
    for (int o = 128; o > 0; o >>= 1) {
        if (threadIdx.x < o) sh[threadIdx.x] += sh[threadIdx.x + o];
        __syncthreads();
    }
    if (threadIdx.x == 0) out[0] = -sh[0] / (float)n;
}

// ---------------------------------------------------------------------------
extern "C" void kernel_launch(void* const* d_in, const int* in_sizes, int n_in,
                              void* d_out, int out_size) {
    const float* E   = (const float*)d_in[0];
    const void*  pos = d_in[1];
    const void*  neg = d_in[2];
    int n = in_sizes[1];   // number of edges

    // 0) detect index dtype (int32 vs int64)
    detect_idx_kernel<<<1, 128>>>(neg, n);

    // 1) normalize + int8 quantize
    int nblk_q = (n + 7) / 8;   // warp per row
    quantize_kernel<<<nblk_q, 256>>>(E, n);

    // 2) int8 IMMA GEMM + positives + logsumexp
    int nblocks = (n + MTILE - 1) / MTILE;
    main_kernel<<<nblocks, 256>>>(pos, neg, n);

    // 3) deterministic reduction into the scalar output
    finalize_kernel<<<1, 256>>>((float*)d_out, n, nblocks);
}

// round 7
// speedup vs baseline: 1.1589x; 1.1589x over previous
#include <cuda_runtime.h>
#include <cuda_fp16.h>
#include <math.h>
#include <stdint.h>

#define NMAX      500000
#define DIM       128
#define SNEG      256
#define STRIDE    136          // padded fp16 row stride (conflict-free fragment LDS)
#define MTILE     256          // rows per block
#define INV_T     10.0f
#define LOG_S     5.545177444479562f   // log(256)
#define MAXBLOCKS 4096

// Scratch: normalized embeddings in fp16 (128MB) + per-block partials.
__device__ __half   g_Qn[(size_t)NMAX * DIM];
__device__ float    g_partial[MAXBLOCKS];
__device__ unsigned g_done;    // ticket counter (reset by last block each launch)

// ---------------------------------------------------------------------------
// Kernel 1: L2-normalize each row of E into fp16. One warp per row.
// (values are <=1 after normalization: fp16 eps 4.9e-4 beats bf16 here)
// ---------------------------------------------------------------------------
__global__ void normalize_kernel(const float* __restrict__ E, int n) {
    int row  = (int)((blockIdx.x * (long long)blockDim.x + threadIdx.x) >> 5);
    int lane = threadIdx.x & 31;
    if (row >= n) return;
    float4 v = reinterpret_cast<const float4*>(E + (size_t)row * DIM)[lane];
    float ss = v.x * v.x + v.y * v.y + v.z * v.z + v.w * v.w;
#pragma unroll
    for (int o = 16; o > 0; o >>= 1) ss += __shfl_xor_sync(0xffffffffu, ss, o);
    float inv = 1.0f / fmaxf(sqrtf(ss), 1e-12f);
    __half2 p0 = __floats2half2_rn(v.x * inv, v.y * inv);
    __half2 p1 = __floats2half2_rn(v.z * inv, v.w * inv);
    uint2 st;
    st.x = reinterpret_cast<unsigned&>(p0);
    st.y = reinterpret_cast<unsigned&>(p1);
    reinterpret_cast<uint2*>(g_Qn + (size_t)row * DIM)[lane] = st;
}

__device__ __forceinline__ float pairdot(unsigned a, unsigned b) {
    float2 fa = __half22float2(*reinterpret_cast<__half2*>(&a));
    float2 fb = __half22float2(*reinterpret_cast<__half2*>(&b));
    return fa.x * fb.x + fa.y * fb.y;
}

// ---------------------------------------------------------------------------
// Kernel 2: per 256-row tile — positives + fp16-acc MMA vs 256 negatives +
// fused logsumexp; last block folds the final reduction (deterministic).
// ---------------------------------------------------------------------------
__global__ __launch_bounds__(256, 2) void main_kernel(
    const void* __restrict__ pos_idx,
    const void* __restrict__ neg_idx,
    float* __restrict__ out,
    int n, int nblocks)
{
    extern __shared__ char smem_raw[];
    __half* sV = reinterpret_cast<__half*>(smem_raw);
    float* sPos = reinterpret_cast<float*>(sV + SNEG * STRIDE);
    float* sRed = sPos + MTILE;

    const int tid  = threadIdx.x;
    const int lane = tid & 31;
    const int warp = tid >> 5;
    const long long tile0 = (long long)blockIdx.x * MTILE;

    // ---- inline index-dtype detection (first 1KB of negatives) -------------
    int ok = 1;
    if (tid < 128) {
        long long v = ((const long long*)neg_idx)[tid];
        ok = (v >= 0 && v < (long long)n);
    }
    const int is64 = __syncthreads_and(ok);

    // ---- stage all 256 negatives into padded smem (1 thread/row) -----------
    {
        long long vr = is64 ? ((const long long*)neg_idx)[tid]
                            : (long long)((const int*)neg_idx)[tid];
        const uint4* src = reinterpret_cast<const uint4*>(g_Qn + (size_t)vr * DIM);
        uint4* dst = reinterpret_cast<uint4*>(sV + tid * STRIDE);
#pragma unroll
        for (int j = 0; j < 16; j++) dst[j] = src[j];
    }

    // ---- positive logits: one thread per row, fp32 dot ---------------------
    {
        long long row = tile0 + tid;
        float dot = 0.0f;
        if (row < n) {
            long long p = is64 ? ((const long long*)pos_idx)[row]
                               : (long long)((const int*)pos_idx)[row];
            const uint4* qa = reinterpret_cast<const uint4*>(g_Qn + (size_t)row * DIM);
            const uint4* qb = reinterpret_cast<const uint4*>(g_Qn + (size_t)p * DIM);
#pragma unroll
            for (int j = 0; j < 16; j++) {
                uint4 a = qa[j], b = qb[j];
                dot += pairdot(a.x, b.x) + pairdot(a.y, b.y)
                     + pairdot(a.z, b.z) + pairdot(a.w, b.w);
            }
        }
        sPos[tid] = dot * INV_T;
    }
    __syncthreads();

    // ---- GEMM: warp = 32 rows x 256 negs, 4 chunks of 64, fp16 accum -------
    const int g  = lane >> 2;     // 0..7
    const int t4 = lane & 3;      // 0..3
    const long long rowG = tile0 + warp * 32 + g;

    float rs[2][2] = {{0.f, 0.f}, {0.f, 0.f}};      // [Ttile][half(row/row+8)]

#pragma unroll
    for (int c = 0; c < 4; c++) {
        unsigned acc[2][8][2];                       // f16x2 accumulators
#pragma unroll
        for (int T = 0; T < 2; T++)
#pragma unroll
            for (int i = 0; i < 8; i++) { acc[T][i][0] = 0u; acc[T][i][1] = 0u; }

#pragma unroll
        for (int k0 = 0; k0 < 8; k0++) {
            const int k = k0 * 16 + 2 * t4;
            unsigned afr[2][4];
#pragma unroll
            for (int T = 0; T < 2; T++) {
                long long r0 = rowG + T * 16;
                long long r1 = r0 + 8;
                bool v0 = r0 < n, v1 = r1 < n;
                const unsigned* p0 = reinterpret_cast<const unsigned*>(
                    g_Qn + (size_t)r0 * DIM + k);
                const unsigned* p1 = reinterpret_cast<const unsigned*>(
                    g_Qn + (size_t)r1 * DIM + k);
                afr[T][0] = v0 ? p0[0] : 0u;
                afr[T][1] = v1 ? p1[0] : 0u;
                afr[T][2] = v0 ? p0[4] : 0u;     // +8 elements
                afr[T][3] = v1 ? p1[4] : 0u;
            }
#pragma unroll
            for (int nt = 0; nt < 8; nt++) {
                const __half* vp = sV + (c * 64 + nt * 8 + g) * STRIDE
                                 + 2 * t4 + k0 * 16;
                unsigned b0 = *reinterpret_cast<const unsigned*>(vp);
                unsigned b1 = *reinterpret_cast<const unsigned*>(vp + 8);
#pragma unroll
                for (int T = 0; T < 2; T++) {
                    asm volatile(
                        "mma.sync.aligned.m16n8k16.row.col.f16.f16.f16.f16 "
                        "{%0,%1}, {%2,%3,%4,%5}, {%6,%7}, {%0,%1};\n"
                        : "+r"(acc[T][nt][0]), "+r"(acc[T][nt][1])
                        : "r"(afr[T][0]), "r"(afr[T][1]),
                          "r"(afr[T][2]), "r"(afr[T][3]),
                          "r"(b0), "r"(b1));
                }
            }
        }
        // ---- exp-accumulate this 64-neg chunk (|logit|<=10, no max) --------
#pragma unroll
        for (int T = 0; T < 2; T++)
#pragma unroll
            for (int nt = 0; nt < 8; nt++) {
                float2 lo = __half22float2(
                    *reinterpret_cast<__half2*>(&acc[T][nt][0]));
                float2 hi = __half22float2(
                    *reinterpret_cast<__half2*>(&acc[T][nt][1]));
                rs[T][0] += __expf(lo.x * INV_T) + __expf(lo.y * INV_T);
                rs[T][1] += __expf(hi.x * INV_T) + __expf(hi.y * INV_T);
            }
    }

    // reduce exp-sums across the 4 lanes of each row group
#pragma unroll
    for (int T = 0; T < 2; T++) {
        rs[T][0] += __shfl_xor_sync(0xffffffffu, rs[T][0], 1);
        rs[T][0] += __shfl_xor_sync(0xffffffffu, rs[T][0], 2);
        rs[T][1] += __shfl_xor_sync(0xffffffffu, rs[T][1], 1);
        rs[T][1] += __shfl_xor_sync(0xffffffffu, rs[T][1], 2);
    }

    float contrib = 0.0f;
    if (t4 == 0) {
#pragma unroll
        for (int T = 0; T < 2; T++) {
            long long r0 = rowG + T * 16;
            if (r0 < n)
                contrib += sPos[warp * 32 + T * 16 + g]
                         - (logf(rs[T][0]) - LOG_S);
            if (r0 + 8 < n)
                contrib += sPos[warp * 32 + T * 16 + g + 8]
                         - (logf(rs[T][1]) - LOG_S);
        }
    }
#pragma unroll
    for (int o = 16; o > 0; o >>= 1)
        contrib += __shfl_xor_sync(0xffffffffu, contrib, o);
    if (lane == 0) sRed[warp] = contrib;
    __syncthreads();

    // ---- publish partial; last block does the deterministic final sum ------
    __shared__ int sLast;
    if (tid == 0) {
        float s = 0.0f;
#pragma unroll
        for (int w = 0; w < 8; w++) s += sRed[w];
        g_partial[blockIdx.x] = s;
        __threadfence();
        unsigned t = atomicAdd(&g_done, 1u);
        sLast = (t == (unsigned)(nblocks - 1));
    }
    __syncthreads();
    if (sLast) {
        float s = 0.0f;
        for (int i = tid; i < nblocks; i += 256) s += g_partial[i];
        sRed[0] = 0.f;   // reuse smem for tree
        __syncthreads();
        sPos[tid] = s;
        __syncthreads();
        for (int o = 128; o > 0; o >>= 1) {
            if (tid < o) sPos[tid] += sPos[tid + o];
            __syncthreads();
        }
        if (tid == 0) {
            out[0] = -sPos[0] / (float)n;
            g_done = 0;                  // reset for next graph replay
        }
    }
}

// ---------------------------------------------------------------------------
extern "C" void kernel_launch(void* const* d_in, const int* in_sizes, int n_in,
                              void* d_out, int out_size) {
    const float* E   = (const float*)d_in[0];
    const void*  pos = d_in[1];
    const void*  neg = d_in[2];
    int n = in_sizes[1];   // number of edges

    // 1) normalize rows -> fp16
    int nblk_norm = (n + 7) / 8;
    normalize_kernel<<<nblk_norm, 256>>>(E, n);

    // 2) fused positives + fp16-acc GEMM + logsumexp + final reduction
    int nblocks = (n + MTILE - 1) / MTILE;
    size_t smem = (size_t)(SNEG * STRIDE) * sizeof(__half)
                + (size_t)(MTILE + 8) * sizeof(float);
    cudaFuncSetAttribute(main_kernel,
                         cudaFuncAttributeMaxDynamicSharedMemorySize, (int)smem);
    main_kernel<<<nblocks, 256, smem>>>(pos, neg, (float*)d_out, n, nblocks);
}

// round 9
// speedup vs baseline: 1.5602x; 1.3462x over previous
#include <cuda_runtime.h>
#include <cuda_fp16.h>
#include <math.h>
#include <stdint.h>

#define NMAX      500000
#define DIM       128
#define SNEG      256
#define STRIDE    136          // fp16 units -> 272B row stride (data 256B + 16B pad)
#define MTILE     256          // rows per block
#define INV_T     10.0f
#define LOG_S     5.545177444479562f    // log(256)
#define BSCALE    14.426950408889634f   // INV_T * log2(e), folded into staged B
#define MAXBLOCKS 4096

__device__ __half    g_Qn[(size_t)NMAX * DIM];
__device__ float     g_partial[MAXBLOCKS];
__device__ unsigned  g_done;

// ---------------------------------------------------------------------------
__global__ void normalize_kernel(const float* __restrict__ E, int n) {
    int row  = (int)((blockIdx.x * (long long)blockDim.x + threadIdx.x) >> 5);
    int lane = threadIdx.x & 31;
    if (row >= n) return;
    float4 v = reinterpret_cast<const float4*>(E + (size_t)row * DIM)[lane];
    float ss = v.x * v.x + v.y * v.y + v.z * v.z + v.w * v.w;
#pragma unroll
    for (int o = 16; o > 0; o >>= 1) ss += __shfl_xor_sync(0xffffffffu, ss, o);
    float inv = 1.0f / fmaxf(sqrtf(ss), 1e-12f);
    __half2 p0 = __floats2half2_rn(v.x * inv, v.y * inv);
    __half2 p1 = __floats2half2_rn(v.z * inv, v.w * inv);
    uint2 st;
    st.x = reinterpret_cast<unsigned&>(p0);
    st.y = reinterpret_cast<unsigned&>(p1);
    reinterpret_cast<uint2*>(g_Qn + (size_t)row * DIM)[lane] = st;
}

__device__ __forceinline__ float pairdot(unsigned a, unsigned b) {
    float2 fa = __half22float2(*reinterpret_cast<__half2*>(&a));
    float2 fb = __half22float2(*reinterpret_cast<__half2*>(&b));
    return fa.x * fb.x + fa.y * fb.y;
}

__device__ __forceinline__ uint32_t smem_u32(const void* p) {
    uint32_t a;
    asm("{ .reg .u64 t; cvta.to.shared.u64 t, %1; cvt.u32.u64 %0, t; }"
        : "=r"(a) : "l"(p));
    return a;
}

__device__ __forceinline__ float ex2f(float x) {
    float y;
    asm("ex2.approx.ftz.f32 %0, %1;" : "=f"(y) : "f"(x));
    return y;
}

// ---------------------------------------------------------------------------
// main: per 256-row tile, positives + fp16-acc MMA (A hoisted, B via ldmatrix)
// + fused logsumexp; last block folds the deterministic final reduction.
// ---------------------------------------------------------------------------
__global__ __launch_bounds__(256, 2) void main_kernel(
    const void* __restrict__ pos_idx,
    const void* __restrict__ neg_idx,
    float* __restrict__ out,
    int n, int nblocks)
{
    extern __shared__ char smem_raw[];
    __half* sV  = reinterpret_cast<__half*>(smem_raw);          // 256*136 fp16
    float* sPos = reinterpret_cast<float*>(sV + SNEG * STRIDE); // 256 floats
    float* sRed = sPos + MTILE;                                  // 8 floats
    int*   sLastP = reinterpret_cast<int*>(sRed + 8);

    const int tid  = threadIdx.x;
    const int lane = tid & 31;
    const int warp = tid >> 5;
    const long long tile0 = (long long)blockIdx.x * MTILE;

    // ---- inline index-dtype detection (first 1KB of negatives) -------------
    int ok = 1;
    if (tid < 128) {
        long long v = ((const long long*)neg_idx)[tid];
        ok = (v >= 0 && v < (long long)n);
    }
    const int is64 = __syncthreads_and(ok);

    // ---- stage 256 negatives, pre-scaled by INV_T*log2e (1 thread/row) -----
    {
        long long vr = is64 ? ((const long long*)neg_idx)[tid]
                            : (long long)((const int*)neg_idx)[tid];
        const uint4* src = reinterpret_cast<const uint4*>(g_Qn + (size_t)vr * DIM);
        uint4* dst = reinterpret_cast<uint4*>(sV + tid * STRIDE);
        const __half2 sc = __float2half2_rn(BSCALE);
#pragma unroll
        for (int j = 0; j < 16; j++) {
            uint4 v = src[j];
            __half2* h = reinterpret_cast<__half2*>(&v);
            h[0] = __hmul2(h[0], sc);
            h[1] = __hmul2(h[1], sc);
            h[2] = __hmul2(h[2], sc);
            h[3] = __hmul2(h[3], sc);
            dst[j] = v;
        }
    }

    // ---- positive logits: one thread per row ----
    {
        long long row = tile0 + tid;
        float dot = 0.0f;
        if (row < n) {
            long long p = is64 ? ((const long long*)pos_idx)[row]
                               : (long long)((const int*)pos_idx)[row];
            const uint4* qa = reinterpret_cast<const uint4*>(g_Qn + (size_t)row * DIM);
            const uint4* qb = reinterpret_cast<const uint4*>(g_Qn + (size_t)p * DIM);
#pragma unroll
            for (int j = 0; j < 16; j++) {
                uint4 a = qa[j], b = qb[j];
                dot += pairdot(a.x, b.x) + pairdot(a.y, b.y)
                     + pairdot(a.z, b.z) + pairdot(a.w, b.w);
            }
        }
        sPos[tid] = dot * INV_T;
    }
    __syncthreads();

    // ---- GEMM: warp = 32 rows (2 T-tiles) x 256 negs ----
    const int g  = lane >> 2;
    const int t4 = lane & 3;
    const long long rowG = tile0 + warp * 32 + g;

    // hoist ALL A fragments (loaded once per tile, reused by all 4 chunks)
    unsigned afr[2][8][4];
#pragma unroll
    for (int T = 0; T < 2; T++) {
        long long r0 = rowG + T * 16;
        long long r1 = r0 + 8;
        const bool v0 = r0 < n, v1 = r1 < n;
        const unsigned* p0 = reinterpret_cast<const unsigned*>(
            g_Qn + (size_t)r0 * DIM + 2 * t4);
        const unsigned* p1 = reinterpret_cast<const unsigned*>(
            g_Qn + (size_t)r1 * DIM + 2 * t4);
#pragma unroll
        for (int k0 = 0; k0 < 8; k0++) {
            afr[T][k0][0] = v0 ? p0[k0 * 8]     : 0u;
            afr[T][k0][1] = v1 ? p1[k0 * 8]     : 0u;
            afr[T][k0][2] = v0 ? p0[k0 * 8 + 4] : 0u;
            afr[T][k0][3] = v1 ? p1[k0 * 8 + 4] : 0u;
        }
    }

    // ldmatrix lane->row map: lanes 0-7: n 0-7 (k lo) | 8-15: n 0-7 (k hi)
    //                         lanes 16-23: n 8-15 (k lo) | 24-31: n 8-15 (k hi)
    const int nrow = (lane & 7) + ((lane & 16) >> 1);
    const uint32_t bAddr = smem_u32(sV) + nrow * (STRIDE * 2)
                         + ((lane & 8) << 1);

    float rs[2][2] = {{0.f, 0.f}, {0.f, 0.f}};

#pragma unroll
    for (int c = 0; c < 4; c++) {
        unsigned acc[2][8][2];
#pragma unroll
        for (int T = 0; T < 2; T++)
#pragma unroll
            for (int i = 0; i < 8; i++) { acc[T][i][0] = 0u; acc[T][i][1] = 0u; }

#pragma unroll
        for (int k0 = 0; k0 < 8; k0++) {
#pragma unroll
            for (int nt2 = 0; nt2 < 4; nt2++) {
                unsigned b0, b1, b2, b3;
                uint32_t a = bAddr + (c * 64 + nt2 * 16) * (STRIDE * 2) + k0 * 32;
                asm volatile(
                    "ldmatrix.sync.aligned.m8n8.x4.shared.b16 "
                    "{%0,%1,%2,%3}, [%4];"
                    : "=r"(b0), "=r"(b1), "=r"(b2), "=r"(b3) : "r"(a));
#pragma unroll
                for (int T = 0; T < 2; T++) {
                    asm volatile(
                        "mma.sync.aligned.m16n8k16.row.col.f16.f16.f16.f16 "
                        "{%0,%1}, {%2,%3,%4,%5}, {%6,%7}, {%0,%1};\n"
                        : "+r"(acc[T][nt2 * 2][0]), "+r"(acc[T][nt2 * 2][1])
                        : "r"(afr[T][k0][0]), "r"(afr[T][k0][1]),
                          "r"(afr[T][k0][2]), "r"(afr[T][k0][3]),
                          "r"(b0), "r"(b1));
                    asm volatile(
                        "mma.sync.aligned.m16n8k16.row.col.f16.f16.f16.f16 "
                        "{%0,%1}, {%2,%3,%4,%5}, {%6,%7}, {%0,%1};\n"
                        : "+r"(acc[T][nt2 * 2 + 1][0]), "+r"(acc[T][nt2 * 2 + 1][1])
                        : "r"(afr[T][k0][0]), "r"(afr[T][k0][1]),
                          "r"(afr[T][k0][2]), "r"(afr[T][k0][3]),
                          "r"(b2), "r"(b3));
                }
            }
        }
        // ---- epilogue: acc already holds logit*log2e -> ex2 directly ----
#pragma unroll
        for (int T = 0; T < 2; T++)
#pragma unroll
            for (int nt = 0; nt < 8; nt++) {
                float2 lo = __half22float2(
                    *reinterpret_cast<__half2*>(&acc[T][nt][0]));
                float2 hi = __half22float2(
                    *reinterpret_cast<__half2*>(&acc[T][nt][1]));
                rs[T][0] += ex2f(lo.x) + ex2f(lo.y);
                rs[T][1] += ex2f(hi.x) + ex2f(hi.y);
            }
    }

    // reduce exp-sums across the 4 lanes of each row group
#pragma unroll
    for (int T = 0; T < 2; T++) {
        rs[T][0] += __shfl_xor_sync(0xffffffffu, rs[T][0], 1);
        rs[T][0] += __shfl_xor_sync(0xffffffffu, rs[T][0], 2);
        rs[T][1] += __shfl_xor_sync(0xffffffffu, rs[T][1], 1);
        rs[T][1] += __shfl_xor_sync(0xffffffffu, rs[T][1], 2);
    }

    float contrib = 0.0f;
    if (t4 == 0) {
#pragma unroll
        for (int T = 0; T < 2; T++) {
            long long r0 = rowG + T * 16;
            if (r0 < n)
                contrib += sPos[warp * 32 + T * 16 + g]
                         - (logf(rs[T][0]) - LOG_S);
            if (r0 + 8 < n)
                contrib += sPos[warp * 32 + T * 16 + g + 8]
                         - (logf(rs[T][1]) - LOG_S);
        }
    }
#pragma unroll
    for (int o = 16; o > 0; o >>= 1)
        contrib += __shfl_xor_sync(0xffffffffu, contrib, o);
    if (lane == 0) sRed[warp] = contrib;
    __syncthreads();

    // ---- publish partial; last block does the deterministic final sum ------
    if (tid == 0) {
        float s = 0.0f;
#pragma unroll
        for (int w = 0; w < 8; w++) s += sRed[w];
        g_partial[blockIdx.x] = s;
        __threadfence();
        unsigned t = atomicAdd(&g_done, 1u);
        *sLastP = (t == (unsigned)(nblocks - 1));
    }
    __syncthreads();
    if (*sLastP) {
        float s = 0.0f;
        for (int i = tid; i < nblocks; i += 256) s += g_partial[i];
        __syncthreads();
        sPos[tid] = s;
        __syncthreads();
        for (int o = 128; o > 0; o >>= 1) {
            if (tid < o) sPos[tid] += sPos[tid + o];
            __syncthreads();
        }
        if (tid == 0) {
            out[0] = -sPos[0] / (float)n;
            g_done = 0;                  // reset for next graph replay
        }
    }
}

// ---------------------------------------------------------------------------
extern "C" void kernel_launch(void* const* d_in, const int* in_sizes, int n_in,
                              void* d_out, int out_size) {
    const float* E   = (const float*)d_in[0];
    const void*  pos = d_in[1];
    const void*  neg = d_in[2];
    int n = in_sizes[1];   // number of edges

    int nblk_norm = (n + 7) / 8;
    normalize_kernel<<<nblk_norm, 256>>>(E, n);

    int nblocks = (n + MTILE - 1) / MTILE;
    size_t smem = (size_t)(SNEG * STRIDE) * sizeof(__half)
                + (size_t)(MTILE + 8 + 4) * sizeof(float);
    cudaFuncSetAttribute(main_kernel,
                         cudaFuncAttributeMaxDynamicSharedMemorySize, (int)smem);
    main_kernel<<<nblocks, 256, smem>>>(pos, neg, (float*)d_out, n, nblocks);
}